// round 5
// baseline (speedup 1.0000x reference)
#include <cuda_runtime.h>
#include <cuda_fp16.h>
#include <math.h>
#include <stdint.h>

// Problem constants
#define RES    8192
#define TSTEPS 1024
#define SDIM   128

// Main kernel config
#define NBLK    128     // persistent blocks, 1 per SM (148 SMs available)
#define RPB     64      // rows of W_res per block (128*64 = 8192)
#define THREADS 1024    // 32 warps, 2 rows per warp
#define CPIN    1536    // columns pinned in SMEM per row (64*1536*2B = 192KB)

// Scratch (static device globals -- no allocations allowed)
__device__ __half  g_Wh[(size_t)RES * RES];            // 128 MB fp16 weights
__device__ float   g_inproj[(size_t)TSTEPS * RES];     // 32 MB
__device__ float   g_rbuf[2][RES];                     // double-buffered state
__device__ unsigned g_count;                           // barrier arrivals
__device__ unsigned g_gen;                             // barrier generation

// ---------------------------------------------------------------------------
// fp32 -> fp16 weight conversion (grid covers exactly RES*RES/4 float4s)
// ---------------------------------------------------------------------------
__global__ void convert_kernel(const float* __restrict__ W) {
    size_t i = ((size_t)blockIdx.x * blockDim.x + threadIdx.x) * 4;
    float4 v = *(const float4*)(W + i);
    __half2* o = (__half2*)(g_Wh + i);
    o[0] = __floats2half2_rn(v.x, v.y);
    o[1] = __floats2half2_rn(v.z, v.w);
}

// ---------------------------------------------------------------------------
// in_proj[t][j] = b[j] + sum_k in_seq[t][k] * W_in[j][k]
// grid (64 j-tiles of 128, 16 t-tiles of 64), 128 threads
// ---------------------------------------------------------------------------
__global__ void inproj_kernel(const float* __restrict__ in_seq,
                              const float* __restrict__ W_in,
                              const float* __restrict__ b_res) {
    extern __shared__ float sm[];
    float* Ws = sm;                 // [128][129] padded
    float* Us = sm + 128 * 129;     // [64][128]
    const int jb  = blockIdx.x * 128;
    const int tb  = blockIdx.y * 64;
    const int tid = threadIdx.x;

    for (int idx = tid; idx < 128 * 128; idx += 128) {
        int r = idx >> 7, k = idx & 127;
        Ws[r * 129 + k] = W_in[(size_t)(jb + r) * SDIM + k];
    }
    for (int idx = tid; idx < 64 * 128; idx += 128) {
        int t = idx >> 7, k = idx & 127;
        Us[idx] = in_seq[(size_t)(tb + t) * SDIM + k];
    }
    __syncthreads();

    const int j = jb + tid;
    const float bj = b_res[j];
    for (int tg = 0; tg < 64; tg += 4) {
        float a0 = bj, a1 = bj, a2 = bj, a3 = bj;
        #pragma unroll 4
        for (int k = 0; k < 128; k++) {
            float w = Ws[tid * 129 + k];
            a0 = fmaf(w, Us[(tg + 0) * 128 + k], a0);
            a1 = fmaf(w, Us[(tg + 1) * 128 + k], a1);
            a2 = fmaf(w, Us[(tg + 2) * 128 + k], a2);
            a3 = fmaf(w, Us[(tg + 3) * 128 + k], a3);
        }
        g_inproj[(size_t)(tb + tg + 0) * RES + j] = a0;
        g_inproj[(size_t)(tb + tg + 1) * RES + j] = a1;
        g_inproj[(size_t)(tb + tg + 2) * RES + j] = a2;
        g_inproj[(size_t)(tb + tg + 3) * RES + j] = a3;
    }
}

// ---------------------------------------------------------------------------
// Persistent recurrent kernel: 1024 sequential steps with a software
// grid barrier. Each block owns 64 rows; first CPIN columns of its slice
// live in SMEM, the remainder streams from L2 (106.5 MB working set < L2).
// ---------------------------------------------------------------------------
__global__ void __launch_bounds__(THREADS, 1)
esn_kernel(const float* __restrict__ res_state, float* __restrict__ out) {
    extern __shared__ char smraw[];
    float*  r_s  = (float*)smraw;                       // 32 KB state copy
    __half* wpin = (__half*)(smraw + RES * sizeof(float));  // 192 KB pinned W

    const int tid   = threadIdx.x;
    const int rbase = blockIdx.x * RPB;

    // Pin first CPIN columns of this block's 64 rows into SMEM (uint4 = 8 halves)
    for (int idx = tid; idx < RPB * CPIN / 8; idx += THREADS) {
        int r = idx / (CPIN / 8);
        int c = idx % (CPIN / 8);
        *(uint4*)(wpin + r * CPIN + c * 8) =
            *(const uint4*)(g_Wh + (size_t)(rbase + r) * RES + c * 8);
    }

    unsigned gen = 0;
    if (tid == 0) gen = *((volatile unsigned*)&g_gen);

    const int w    = tid >> 5;
    const int lane = tid & 31;
    const int lr0  = 2 * w;                        // local row pair
    const __half* gw0 = g_Wh + (size_t)(rbase + lr0) * RES;
    const __half* gw1 = gw0 + RES;
    const __half* sp0 = wpin + lr0 * CPIN;
    const __half* sp1 = sp0 + CPIN;

    for (int t = 0; t < TSTEPS; t++) {
        // Load current state into SMEM. Cross-SM producer -> must bypass L1.
        const float* rsrc = (t == 0) ? res_state : g_rbuf[(t + 1) & 1];
        for (int i = tid; i < RES / 4; i += THREADS)
            ((float4*)r_s)[i] = __ldcg((const float4*)rsrc + i);
        __syncthreads();

        float a0 = 0.f, b0 = 0.f, a1 = 0.f, b1 = 0.f;

        // SMEM-pinned columns [0, CPIN)
        #pragma unroll
        for (int it = 0; it < CPIN / 128; it++) {
            int c = it * 128 + 4 * lane;
            uint2 q0 = *(const uint2*)(sp0 + c);
            uint2 q1 = *(const uint2*)(sp1 + c);
            float4 rv = *(const float4*)(r_s + c);
            float2 u;
            u = __half22float2(*(__half2*)&q0.x);
            a0 = fmaf(u.x, rv.x, a0); b0 = fmaf(u.y, rv.y, b0);
            u = __half22float2(*(__half2*)&q0.y);
            a0 = fmaf(u.x, rv.z, a0); b0 = fmaf(u.y, rv.w, b0);
            u = __half22float2(*(__half2*)&q1.x);
            a1 = fmaf(u.x, rv.x, a1); b1 = fmaf(u.y, rv.y, b1);
            u = __half22float2(*(__half2*)&q1.y);
            a1 = fmaf(u.x, rv.z, a1); b1 = fmaf(u.y, rv.w, b1);
        }

        // L2-streamed columns [CPIN, RES)
        #pragma unroll 4
        for (int it = 0; it < (RES - CPIN) / 128; it++) {
            int c = CPIN + it * 128 + 4 * lane;
            uint2 q0 = *(const uint2*)(gw0 + c);
            uint2 q1 = *(const uint2*)(gw1 + c);
            float4 rv = *(const float4*)(r_s + c);
            float2 u;
            u = __half22float2(*(__half2*)&q0.x);
            a0 = fmaf(u.x, rv.x, a0); b0 = fmaf(u.y, rv.y, b0);
            u = __half22float2(*(__half2*)&q0.y);
            a0 = fmaf(u.x, rv.z, a0); b0 = fmaf(u.y, rv.w, b0);
            u = __half22float2(*(__half2*)&q1.x);
            a1 = fmaf(u.x, rv.x, a1); b1 = fmaf(u.y, rv.y, b1);
            u = __half22float2(*(__half2*)&q1.y);
            a1 = fmaf(u.x, rv.z, a1); b1 = fmaf(u.y, rv.w, b1);
        }

        float s0 = a0 + b0, s1 = a1 + b1;
        #pragma unroll
        for (int off = 16; off; off >>= 1) {
            s0 += __shfl_xor_sync(0xffffffffu, s0, off);
            s1 += __shfl_xor_sync(0xffffffffu, s1, off);
        }

        if (lane == 0) {
            int r0 = rbase + lr0;
            const float* ip = g_inproj + (size_t)t * RES;
            float y0 = tanhf(s0 + ip[r0]);
            float y1 = tanhf(s1 + ip[r0 + 1]);
            float* nb = g_rbuf[t & 1];
            nb[r0] = y0; nb[r0 + 1] = y1;
            out[(size_t)t * RES + r0]     = y0;
            out[(size_t)t * RES + r0 + 1] = y1;
            __threadfence();   // release this warp's state writes
        }

        // ---- grid-wide barrier (sense via generation counter) ----
        __syncthreads();
        if (tid == 0) {
            gen++;
            unsigned prev = atomicAdd(&g_count, 1u);
            if (prev == NBLK - 1) {
                atomicExch(&g_count, 0u);
                __threadfence();
                *((volatile unsigned*)&g_gen) = gen;
            } else {
                while (*((volatile unsigned*)&g_gen) != gen) { __nanosleep(40); }
            }
            __threadfence();   // acquire
        }
        __syncthreads();
    }
}

// ---------------------------------------------------------------------------
// Inputs (metadata order): in_seq[1024,128], res_state[8192],
//                          W_in[8192,128], W_res[8192,8192], b_res[8192]
// Output: res_seq[1024,8192] float32
// ---------------------------------------------------------------------------
extern "C" void kernel_launch(void* const* d_in, const int* in_sizes, int n_in,
                              void* d_out, int out_size) {
    const float* in_seq    = (const float*)d_in[0];
    const float* res_state = (const float*)d_in[1];
    const float* W_in      = (const float*)d_in[2];
    const float* W_res     = (const float*)d_in[3];
    const float* b_res     = (const float*)d_in[4];
    float* out = (float*)d_out;

    // Opt-in SMEM sizes (idempotent; legal during capture -- not stream ops)
    const int inproj_smem = (128 * 129 + 64 * 128) * sizeof(float);  // ~96.5 KB
    const int esn_smem    = RES * sizeof(float) + RPB * CPIN * sizeof(__half); // 224 KB
    cudaFuncSetAttribute(inproj_kernel, cudaFuncAttributeMaxDynamicSharedMemorySize, inproj_smem);
    cudaFuncSetAttribute(esn_kernel,    cudaFuncAttributeMaxDynamicSharedMemorySize, esn_smem);

    // 1) W_res fp32 -> fp16
    {
        size_t n4 = (size_t)RES * RES / 4;      // 16,777,216 float4s
        int threads = 256;
        int blocks  = (int)(n4 / threads);      // exact
        convert_kernel<<<blocks, threads>>>(W_res);
    }

    // 2) in_proj = in_seq @ W_in^T + b
    {
        dim3 grid(RES / 128, TSTEPS / 64);
        inproj_kernel<<<grid, 128, inproj_smem>>>(in_seq, W_in, b_res);
    }

    // 3) persistent recurrent rollout
    esn_kernel<<<NBLK, THREADS, esn_smem>>>(res_state, out);
}